// round 11
// baseline (speedup 1.0000x reference)
#include <cuda_runtime.h>
#include <cuda_bf16.h>
#include <cstdint>

#define Bdim 64
#define Sdim 48
#define MMAX 24
#define KD   25
#define Vdim 2048
#define NBS   (Bdim * Sdim)       // 3072
#define NROWS (NBS * KD)          // 76800
#define NBLK  888                 // 148 SM * 6 CTAs (64 thr, 32KB smem) -> single wave
#define NWARP (NBLK * 2)          // 1776
#define ROWB  (Vdim * 4)          // 8192 bytes per row

__device__ float    g_warp[NWARP];
__device__ int      g_cnt;
__device__ unsigned g_done;       // atomicInc wraps at NBLK-1 -> self-resetting

__device__ __forceinline__ uint32_t smem_u32(const void* p) {
    uint32_t a;
    asm("{ .reg .u64 t; cvta.to.shared.u64 t, %1; cvt.u32.u64 %0, t; }" : "=r"(a) : "l"(p));
    return a;
}
__device__ __forceinline__ void mbar_init(uint32_t mbar, uint32_t cnt) {
    asm volatile("mbarrier.init.shared.b64 [%0], %1;" :: "r"(mbar), "r"(cnt) : "memory");
}
__device__ __forceinline__ void mbar_expect_tx(uint32_t mbar, uint32_t bytes) {
    asm volatile("mbarrier.arrive.expect_tx.shared.b64 _, [%0], %1;" :: "r"(mbar), "r"(bytes) : "memory");
}
__device__ __forceinline__ void mbar_wait(uint32_t mbar, uint32_t parity) {
    asm volatile(
        "{\n\t.reg .pred P;\n\t"
        "W_%=:\n\t"
        "mbarrier.try_wait.parity.acquire.cta.shared::cta.b64 P, [%0], %1, 0x989680;\n\t"
        "@P bra.uni D_%=;\n\t"
        "bra.uni W_%=;\n\t"
        "D_%=:\n\t}"
        :: "r"(mbar), "r"(parity) : "memory");
}
__device__ __forceinline__ void bulk_copy(uint32_t dst, const void* src, uint32_t bytes, uint32_t mbar) {
    asm volatile(
        "cp.async.bulk.shared::cluster.global.mbarrier::complete_tx::bytes [%0], [%1], %2, [%3];"
        :: "r"(dst), "l"(src), "r"(bytes), "r"(mbar) : "memory");
}
__device__ __forceinline__ void fence_async() {
    asm volatile("fence.proxy.async.shared::cta;" ::: "memory");
}

__device__ __forceinline__ bool row_valid(int r, const int* __restrict__ seqlen,
                                          const int* __restrict__ mlen) {
    const int bs = r / KD;
    const int k  = r - bs * KD;
    const int b  = bs / Sdim;
    const int s  = bs - b * Sdim;
    return (s < seqlen[b]) && (k <= mlen[bs]);
}
__device__ __forceinline__ int next_valid(int r, const int* __restrict__ seqlen,
                                          const int* __restrict__ mlen) {
    while (r < NROWS && !row_valid(r, seqlen, mlen)) r += NWARP;
    return r;
}

__global__ __launch_bounds__(64) void ce_kernel(
    const int*   __restrict__ labels,     // [B,S,MMAX]
    const float* __restrict__ logits,     // [B,S,K,V]
    const int*   __restrict__ seqlen,     // [B]
    const int*   __restrict__ mlen,       // [B,S]
    const int*   __restrict__ endtok,     // [1] or null
    float*       __restrict__ out)
{
    __shared__ __align__(128) float buf[2][2][Vdim];   // [warp][stage][row]  32 KB
    __shared__ uint64_t mbar_s[2][2];

    const int w  = threadIdx.x >> 5;      // 0..1
    const int l  = threadIdx.x & 31;
    const int gw = blockIdx.x * 2 + w;
    const int et = endtok ? endtok[0] : (Vdim - 1);

    uint32_t mb[2]   = { smem_u32(&mbar_s[w][0]), smem_u32(&mbar_s[w][1]) };
    uint32_t bsm[2]  = { smem_u32(&buf[w][0][0]), smem_u32(&buf[w][1][0]) };

    if (l == 0) { mbar_init(mb[0], 1); mbar_init(mb[1], 1); }
    fence_async();
    __syncwarp();

    float acc = 0.0f;
    int   cnt = 0;
    int   par[2] = {0, 0};

    // prologue: two rows in flight
    int r0 = next_valid(gw, seqlen, mlen);
    int r1 = (r0 < NROWS) ? next_valid(r0 + NWARP, seqlen, mlen) : NROWS;
    if (l == 0) {
        if (r0 < NROWS) { mbar_expect_tx(mb[0], ROWB); bulk_copy(bsm[0], logits + (size_t)r0 * Vdim, ROWB, mb[0]); }
        if (r1 < NROWS) { mbar_expect_tx(mb[1], ROWB); bulk_copy(bsm[1], logits + (size_t)r1 * Vdim, ROWB, mb[1]); }
    }

    int cur = 0;
    while (r0 < NROWS) {
        const int bs = r0 / KD;
        const int k  = r0 - bs * KD;
        const int m  = mlen[bs];
        const int lab = (k == m) ? et : labels[bs * MMAX + k];

        mbar_wait(mb[cur], par[cur]);
        par[cur] ^= 1;

        const float*  bp  = buf[w][cur];
        const float4* bp4 = (const float4*)bp;

        const float xl = bp[lab];   // broadcast smem read

        float sum = 0.0f;
        #pragma unroll
        for (int i = 0; i < 16; i++) {
            float4 v = bp4[l + 32 * i];
            sum += __expf(v.x) + __expf(v.y) + __expf(v.z) + __expf(v.w);
        }
        #pragma unroll
        for (int off = 16; off; off >>= 1)
            sum += __shfl_xor_sync(0xffffffffu, sum, off);

        acc += __logf(sum) - xl;    // identical across warp
        cnt += 1;

        // refill the buffer we just drained (all lanes past the reduction
        // => all smem reads consumed; shfl convergence guarantees it)
        const int r2 = (r1 < NROWS) ? next_valid(r1 + NWARP, seqlen, mlen) : NROWS;
        if (r2 < NROWS && l == 0) {
            fence_async();
            mbar_expect_tx(mb[cur], ROWB);
            bulk_copy(bsm[cur], logits + (size_t)r2 * Vdim, ROWB, mb[cur]);
        }
        r0 = r1; r1 = r2; cur ^= 1;
    }

    // per-warp partial; per-CTA exact count
    __shared__ int  scnt[2];
    __shared__ bool is_last;
    if (l == 0) {
        g_warp[gw] = acc;
        scnt[w] = cnt;
    }
    __syncthreads();
    if (threadIdx.x == 0) {
        atomicAdd(&g_cnt, scnt[0] + scnt[1]);
        __threadfence();
        unsigned ticket = atomicInc(&g_done, NBLK - 1);
        is_last = (ticket == NBLK - 1);
    }
    __syncthreads();

    if (is_last) {
        __threadfence();
        const int t = threadIdx.x;
        float sum = 0.0f;
        for (int i = t; i < NWARP; i += 64)
            sum += g_warp[i];
        #pragma unroll
        for (int off = 16; off; off >>= 1)
            sum += __shfl_xor_sync(0xffffffffu, sum, off);
        __shared__ float ss2[2];
        if (l == 0) ss2[w] = sum;
        __syncthreads();
        if (t == 0) {
            out[0] = (ss2[0] + ss2[1]) / (float)g_cnt;
            g_cnt = 0;   // reset for next graph replay
        }
    }
}

extern "C" void kernel_launch(void* const* d_in, const int* in_sizes, int n_in,
                              void* d_out, int out_size) {
    const int*   labels = (const int*)  d_in[0];
    const float* logits = (const float*)d_in[1];
    const int*   seqlen = (const int*)  d_in[2];
    const int*   mlen   = (const int*)  d_in[3];
    const int*   endtok = (n_in > 5) ? (const int*)d_in[5] : nullptr;
    float* out = (float*)d_out;

    ce_kernel<<<NBLK, 64>>>(labels, logits, seqlen, mlen, endtok, out);
}

// round 12
// speedup vs baseline: 1.0692x; 1.0692x over previous
#include <cuda_runtime.h>
#include <cuda_bf16.h>
#include <cstdint>

#define Bdim 64
#define Sdim 48
#define MMAX 24
#define KD   25
#define Vdim 2048
#define NBS   (Bdim * Sdim)       // 3072
#define NROWS (NBS * KD)          // 76800
#define WPB   4
#define NBLK  888                 // 148 SM * 6 CTAs (128 thr, 32KB smem) -> single wave
#define NWARP (NBLK * WPB)        // 3552
#define HALF  1024                // floats per half-row
#define HALFB (HALF * 4)          // 4096 bytes

__device__ float    g_warp[NWARP];
__device__ int      g_cnt;
__device__ unsigned g_done;       // atomicInc wraps at NBLK-1 -> self-resetting

__device__ __forceinline__ uint32_t smem_u32(const void* p) {
    uint32_t a;
    asm("{ .reg .u64 t; cvta.to.shared.u64 t, %1; cvt.u32.u64 %0, t; }" : "=r"(a) : "l"(p));
    return a;
}
__device__ __forceinline__ void mbar_init(uint32_t mbar, uint32_t cnt) {
    asm volatile("mbarrier.init.shared.b64 [%0], %1;" :: "r"(mbar), "r"(cnt) : "memory");
}
__device__ __forceinline__ void mbar_expect_tx(uint32_t mbar, uint32_t bytes) {
    asm volatile("mbarrier.arrive.expect_tx.shared.b64 _, [%0], %1;" :: "r"(mbar), "r"(bytes) : "memory");
}
__device__ __forceinline__ void mbar_wait(uint32_t mbar, uint32_t parity) {
    asm volatile(
        "{\n\t.reg .pred P;\n\t"
        "W_%=:\n\t"
        "mbarrier.try_wait.parity.acquire.cta.shared::cta.b64 P, [%0], %1, 0x989680;\n\t"
        "@P bra.uni D_%=;\n\t"
        "bra.uni W_%=;\n\t"
        "D_%=:\n\t}"
        :: "r"(mbar), "r"(parity) : "memory");
}
__device__ __forceinline__ void bulk_copy(uint32_t dst, const void* src, uint32_t bytes, uint32_t mbar) {
    asm volatile(
        "cp.async.bulk.shared::cluster.global.mbarrier::complete_tx::bytes [%0], [%1], %2, [%3];"
        :: "r"(dst), "l"(src), "r"(bytes), "r"(mbar) : "memory");
}
__device__ __forceinline__ void fence_async() {
    asm volatile("fence.proxy.async.shared::cta;" ::: "memory");
}

__device__ __forceinline__ bool row_valid(int r, const int* __restrict__ seqlen,
                                          const int* __restrict__ mlen) {
    const int bs = r / KD;
    const int k  = r - bs * KD;
    const int b  = bs / Sdim;
    const int s  = bs - b * Sdim;
    return (s < seqlen[b]) && (k <= mlen[bs]);
}
__device__ __forceinline__ int next_valid(int r, const int* __restrict__ seqlen,
                                          const int* __restrict__ mlen) {
    while (r < NROWS && !row_valid(r, seqlen, mlen)) r += NWARP;
    return r;
}

__global__ __launch_bounds__(128, 6) void ce_kernel(
    const int*   __restrict__ labels,     // [B,S,MMAX]
    const float* __restrict__ logits,     // [B,S,K,V]
    const int*   __restrict__ seqlen,     // [B]
    const int*   __restrict__ mlen,       // [B,S]
    const int*   __restrict__ endtok,     // [1] or null
    float*       __restrict__ out)
{
    __shared__ __align__(128) float buf[WPB][2][HALF];   // 32 KB
    __shared__ uint64_t mbar_s[WPB][2];

    const int w  = threadIdx.x >> 5;      // 0..3 -> all 4 SMSPs
    const int l  = threadIdx.x & 31;
    const int gw = blockIdx.x * WPB + w;
    const int et = endtok ? endtok[0] : (Vdim - 1);

    const uint32_t mb0  = smem_u32(&mbar_s[w][0]);
    const uint32_t mb1  = smem_u32(&mbar_s[w][1]);
    const uint32_t bsm0 = smem_u32(&buf[w][0][0]);
    const uint32_t bsm1 = smem_u32(&buf[w][1][0]);

    if (l == 0) { mbar_init(mb0, 1); mbar_init(mb1, 1); }
    fence_async();
    __syncwarp();

    float acc = 0.0f;
    int   cnt = 0;
    int   par0 = 0, par1 = 0;

    int r = next_valid(gw, seqlen, mlen);
    if (r < NROWS && l == 0) {
        const float* src = logits + (size_t)r * Vdim;
        mbar_expect_tx(mb0, HALFB); bulk_copy(bsm0, src,        HALFB, mb0);
        mbar_expect_tx(mb1, HALFB); bulk_copy(bsm1, src + HALF, HALFB, mb1);
    }

    while (r < NROWS) {
        const int bs = r / KD;
        const int k  = r - bs * KD;
        const int m  = mlen[bs];
        const int lab = (k == m) ? et : labels[bs * MMAX + k];

        const int rn = next_valid(r + NWARP, seqlen, mlen);
        const float* srcn = (rn < NROWS) ? (logits + (size_t)rn * Vdim) : nullptr;

        // ---- half 0 ----
        mbar_wait(mb0, par0); par0 ^= 1;
        float xl = (lab < HALF) ? buf[w][0][lab] : 0.0f;   // broadcast read
        float sum = 0.0f;
        {
            const float4* p4 = (const float4*)&buf[w][0][0];
            #pragma unroll
            for (int i = 0; i < 8; i++) {
                float4 v = p4[l + 32 * i];
                sum += __expf(v.x) + __expf(v.y) + __expf(v.z) + __expf(v.w);
            }
        }
        __syncwarp();
        if (srcn && l == 0) {
            fence_async();
            mbar_expect_tx(mb0, HALFB);
            bulk_copy(bsm0, srcn, HALFB, mb0);
        }

        // ---- half 1 (its copy has been in flight all along) ----
        mbar_wait(mb1, par1); par1 ^= 1;
        if (lab >= HALF) xl = buf[w][1][lab - HALF];
        {
            const float4* p4 = (const float4*)&buf[w][1][0];
            #pragma unroll
            for (int i = 0; i < 8; i++) {
                float4 v = p4[l + 32 * i];
                sum += __expf(v.x) + __expf(v.y) + __expf(v.z) + __expf(v.w);
            }
        }
        __syncwarp();
        if (srcn && l == 0) {
            fence_async();
            mbar_expect_tx(mb1, HALFB);
            bulk_copy(bsm1, srcn + HALF, HALFB, mb1);
        }

        // ---- finish row (next row's copies already streaming) ----
        #pragma unroll
        for (int off = 16; off; off >>= 1)
            sum += __shfl_xor_sync(0xffffffffu, sum, off);

        acc += __logf(sum) - xl;
        cnt += 1;
        r = rn;
    }

    // per-warp partial; per-CTA exact count
    __shared__ int  scnt[WPB];
    __shared__ bool is_last;
    if (l == 0) {
        g_warp[gw] = acc;
        scnt[w] = cnt;
    }
    __syncthreads();
    if (threadIdx.x == 0) {
        atomicAdd(&g_cnt, scnt[0] + scnt[1] + scnt[2] + scnt[3]);
        __threadfence();
        unsigned ticket = atomicInc(&g_done, NBLK - 1);
        is_last = (ticket == NBLK - 1);
    }
    __syncthreads();

    if (is_last) {
        __threadfence();
        const int t = threadIdx.x;
        float sum = 0.0f;
        for (int i = t; i < NWARP; i += 128)
            sum += g_warp[i];
        #pragma unroll
        for (int off = 16; off; off >>= 1)
            sum += __shfl_xor_sync(0xffffffffu, sum, off);
        __shared__ float ss2[WPB];
        if (l == 0) ss2[w] = sum;
        __syncthreads();
        if (t == 0) {
            out[0] = (ss2[0] + ss2[1] + ss2[2] + ss2[3]) / (float)g_cnt;
            g_cnt = 0;   // reset for next graph replay
        }
    }
}

extern "C" void kernel_launch(void* const* d_in, const int* in_sizes, int n_in,
                              void* d_out, int out_size) {
    const int*   labels = (const int*)  d_in[0];
    const float* logits = (const float*)d_in[1];
    const int*   seqlen = (const int*)  d_in[2];
    const int*   mlen   = (const int*)  d_in[3];
    const int*   endtok = (n_in > 5) ? (const int*)d_in[5] : nullptr;
    float* out = (float*)d_out;

    ce_kernel<<<NBLK, 128>>>(labels, logits, seqlen, mlen, endtok, out);
}